// round 16
// baseline (speedup 1.0000x reference)
#include <cuda_runtime.h>
#include <cstdint>

// DiscreteTemporalEmbedding — R16: two-phase. Phase 1 precomputes the 64
// distinct 6KB tiles into device scratch; phase 2 is a pure broadcast
// (1 LDG.128 -> 32 streaming stores per thread, no smem/sync prologue).

// Problem constants (fixed by the reference)
#define B_   64
#define T_   24
#define NV_  1024
#define C_   64
#define DPW_ 7
#define TPD_ 288
#define TILE_ (C_ * T_)          // 1536 floats = 6144 bytes per (b, n) slab
#define TILE4_ (TILE_ / 4)       // 384 float4
#define VERTS_PER_BLOCK_ 32
#define THREADS_ 384             // one float4 lane per thread

// 64 tiles x 6KB = 384KB scratch (device global: allocation-guard-safe)
__device__ float g_tiles[B_ * TILE_];

__global__ __launch_bounds__(THREADS_)
void dte_build_kernel(const int* __restrict__ t,
                      const float* __restrict__ W) {
    __shared__ int dow_s[T_];
    __shared__ int tod_s[T_];
    const int b   = blockIdx.x;
    const int tid = threadIdx.x;

    if (tid < T_) {
        int dow = t[(b * T_ + tid) * 2 + 0] % DPW_;
        int tod = t[(b * T_ + tid) * 2 + 1] % TPD_;
        dow_s[tid] = dow * C_;
        tod_s[tid] = (DPW_ + tod) * C_;
    }
    __syncthreads();

    // tile[c][t] = W[dow_t][c] + W[DPW+tod_t][c]  (output layout)
    #pragma unroll
    for (int idx = tid; idx < TILE_; idx += THREADS_) {
        int c  = idx / T_;
        int ti = idx - c * T_;
        g_tiles[b * TILE_ + idx] = W[dow_s[ti] + c] + W[tod_s[ti] + c];
    }
}

__global__ __launch_bounds__(THREADS_)
void dte_bcast_kernel(float* __restrict__ out) {
    // Spread decomposition: consecutive blockIdx.x -> different b.
    const int b      = blockIdx.x & 63;
    const int nchunk = blockIdx.x >> 6;
    const int tid    = threadIdx.x;

    // One coalesced 128-bit load (L2-resident 384KB table), then stream.
    const float4 val =
        reinterpret_cast<const float4*>(g_tiles)[b * TILE4_ + tid];

    float* o = out + ((size_t)b * NV_ + (size_t)nchunk * VERTS_PER_BLOCK_) * TILE_
                   + (size_t)tid * 4;

    #pragma unroll
    for (int v = 0; v < VERTS_PER_BLOCK_; v++) {
        asm volatile(
            "st.global.cs.v4.f32 [%0], {%1,%2,%3,%4};"
            :: "l"(o + (size_t)v * TILE_),
               "f"(val.x), "f"(val.y), "f"(val.z), "f"(val.w)
            : "memory");
    }
}

extern "C" void kernel_launch(void* const* d_in, const int* in_sizes, int n_in,
                              void* d_out, int out_size) {
    const int*   t = (const int*)d_in[0];    // [B, T, 2] int32
    const float* W = (const float*)d_in[1];  // [DPW+TPD, C] float32
    float* out = (float*)d_out;              // [B, N, C, T] float32

    dte_build_kernel<<<B_, THREADS_>>>(t, W);                    // 64 blocks
    dte_bcast_kernel<<<B_ * (NV_ / VERTS_PER_BLOCK_), THREADS_>>>(out);  // 2048
}

// round 17
// speedup vs baseline: 1.0278x; 1.0278x over previous
#include <cuda_runtime.h>
#include <cstdint>

// DiscreteTemporalEmbedding — R17: single kernel, per-thread direct tile
// computation (no smem, no syncthreads), then streaming broadcast.
// Each thread's float4 = 4 tile elements sharing one c, spanning t0..t0+3.

// Problem constants (fixed by the reference)
#define B_   64
#define T_   24
#define NV_  1024
#define C_   64
#define DPW_ 7
#define TPD_ 288
#define TILE_ (C_ * T_)          // 1536 floats = 6144 bytes per (b, n) slab
#define TILE4_ (TILE_ / 4)       // 384 float4
#define VERTS_PER_BLOCK_ 32
#define THREADS_ 384             // one float4 lane per thread

__global__ __launch_bounds__(THREADS_)
void dte_kernel(const int* __restrict__ t,
                const float* __restrict__ W,
                float* __restrict__ out) {
    // Spread decomposition: consecutive blockIdx.x -> different b.
    const int b      = blockIdx.x & 63;
    const int nchunk = blockIdx.x >> 6;
    const int tid    = threadIdx.x;

    // This thread's 4 tile elements: indices 4*tid .. 4*tid+3.
    // T_=24 is a multiple of 4 => all share c; t spans t0..t0+3.
    const int c  = (4 * tid) / T_;
    const int t0 = (4 * tid) - c * T_;        // multiple of 4

    // Two aligned int4 loads fetch the 4 (dow, tod) pairs.
    // &t[(b*T_ + t0)*2] byte offset = b*192 + t0*8: multiple of 16. 
    const int4* tp = reinterpret_cast<const int4*>(t + (b * T_ + t0) * 2);
    const int4 p01 = tp[0];   // dow0, tod0, dow1, tod1
    const int4 p23 = tp[1];   // dow2, tod2, dow3, tod3

    // 8 scalar W loads (18.9KB table, L1-hot) + 4 adds.
    float4 val;
    val.x = W[(p01.x % DPW_) * C_ + c] + W[(DPW_ + p01.y % TPD_) * C_ + c];
    val.y = W[(p01.z % DPW_) * C_ + c] + W[(DPW_ + p01.w % TPD_) * C_ + c];
    val.z = W[(p23.x % DPW_) * C_ + c] + W[(DPW_ + p23.y % TPD_) * C_ + c];
    val.w = W[(p23.z % DPW_) * C_ + c] + W[(DPW_ + p23.w % TPD_) * C_ + c];

    // Streaming broadcast: 32 independent evict-first 128-bit stores.
    float* o = out + ((size_t)b * NV_ + (size_t)nchunk * VERTS_PER_BLOCK_) * TILE_
                   + (size_t)tid * 4;

    #pragma unroll
    for (int v = 0; v < VERTS_PER_BLOCK_; v++) {
        asm volatile(
            "st.global.cs.v4.f32 [%0], {%1,%2,%3,%4};"
            :: "l"(o + (size_t)v * TILE_),
               "f"(val.x), "f"(val.y), "f"(val.z), "f"(val.w)
            : "memory");
    }
}

extern "C" void kernel_launch(void* const* d_in, const int* in_sizes, int n_in,
                              void* d_out, int out_size) {
    const int*   t = (const int*)d_in[0];    // [B, T, 2] int32
    const float* W = (const float*)d_in[1];  // [DPW+TPD, C] float32
    float* out = (float*)d_out;              // [B, N, C, T] float32

    dim3 grid(B_ * (NV_ / VERTS_PER_BLOCK_));  // 2048 blocks
    dte_kernel<<<grid, THREADS_>>>(t, W, out);
}